// round 11
// baseline (speedup 1.0000x reference)
#include <cuda_runtime.h>
#include <math.h>

// Closed-form collapse of the 4-qubit circuit, product-to-sum trig:
//   a  = t1 + p1,  u = cos(a-t0),  v = cos(a+t0)
//   m0 = cos(p4)cos(p0)cos(t0) + (sin(p4)/2)(v - u)
//   m1 = (cos(p0)/2)(u + v)
//   m2 = cos(t2)
//   m3 = cos(p3)cos(t2)cos(t3)
// t2,t3 are raw pixels in [0,1): cos via even minimax poly on the FMA pipe.
// 2-class log_softmax needs only d = l1 - l0 -> single dot vs dW = W[1]-W[0].
// (redux.sync.add.f32 is NOT available on sm_103 — shuffle reduction it is.)
//
// grid=64 (one block per image), 640 threads; threads 0..624 handle exactly
// two patch-pairs; pair B addresses = pair A addresses + fixed immediates.

#define BLK    640
#define ACTIVE 625     // 1250 pairs / 2; 625 = 25*25

// cos(t) for t in [0,1]: even minimax poly, |err| ~ 1e-6
__device__ __forceinline__ float cos01(float t) {
    const float s = t * t;
    return fmaf(s, fmaf(s, fmaf(s, -1.3853704e-3f, 4.1663687e-2f),
                        -4.9999905e-1f), 9.9999994e-1f);
}

__device__ __forceinline__ void patch_dot(
    float t0, float t1, float t2, float t3,
    float K1, float K2h, float K3h, float K4, float P1,
    const float4& dw, float& acc)
{
    const float a   = t1 + P1;
    const float c0  = __cosf(t0);
    const float u   = __cosf(a - t0);
    const float v   = __cosf(a + t0);
    const float ct2 = cos01(t2);          // FMA pipe
    const float ct3 = cos01(t3);          // FMA pipe
    const float m0  = fmaf(K1, c0, K2h * (v - u));
    const float m1  = K3h * (u + v);
    const float m3  = K4 * ct2 * ct3;
    acc = fmaf(m0, dw.x, fmaf(m1, dw.y, fmaf(ct2, dw.z, fmaf(m3, dw.w, acc))));
}

__device__ __forceinline__ float4 f4sub(const float4 a, const float4 b) {
    return make_float4(a.x - b.x, a.y - b.y, a.z - b.z, a.w - b.w);
}

__global__ __launch_bounds__(BLK) void fused_kernel(
    const float* __restrict__ x,
    const float* __restrict__ W,
    const float* __restrict__ bias,
    const float* __restrict__ qp,
    float* __restrict__ out)
{
    const int tid = threadIdx.x;
    const int b   = blockIdx.x;

    // Hoisted: bias difference (overlaps main load wave; avoids tail latency)
    const float dbias = bias[1] - bias[0];

    // Circuit constants (broadcast loads; MUFU overlaps x-load latency)
    float sp4, cp4;
    __sincosf(qp[4], &sp4, &cp4);
    const float cp0 = __cosf(qp[0]);
    const float K4  = __cosf(qp[3]);
    const float P1  = qp[1];
    const float K1  = cp4 * cp0;
    const float K2h = 0.5f * sp4;
    const float K3h = 0.5f * cp0;

    float acc = 0.f;

    if (tid < ACTIVE) {
        const int i  = tid / 25;              // patch row 0..24 (pair A)
        const int jp = tid - i * 25;          // pair column 0..24
        const int p  = i * 50 + 2 * jp;       // patch index (pair A)

        const float* xA = x + b * 10000 + 200 * i + 4 * jp;
        const float* wA = W + p * 4;

        // ---- issue ALL loads up front (12 independent 16B loads,
        //      B-addresses are A-addresses + fixed immediates) ----
        const float4 rA0 = *reinterpret_cast<const float4*>(xA);
        const float4 rA1 = *reinterpret_cast<const float4*>(xA + 100);
        const float4 rB0 = *reinterpret_cast<const float4*>(xA + 5000);
        const float4 rB1 = *reinterpret_cast<const float4*>(xA + 5100);
        const float4 wA00 = *reinterpret_cast<const float4*>(wA);
        const float4 wA01 = *reinterpret_cast<const float4*>(wA + 4);
        const float4 wB00 = *reinterpret_cast<const float4*>(wA + 5000);
        const float4 wB01 = *reinterpret_cast<const float4*>(wA + 5004);
        const float4 wA10 = *reinterpret_cast<const float4*>(wA + 10000);
        const float4 wA11 = *reinterpret_cast<const float4*>(wA + 10004);
        const float4 wB10 = *reinterpret_cast<const float4*>(wA + 15000);
        const float4 wB11 = *reinterpret_cast<const float4*>(wA + 15004);

        const float4 dA0 = f4sub(wA10, wA00);
        const float4 dA1 = f4sub(wA11, wA01);
        const float4 dB0 = f4sub(wB10, wB00);
        const float4 dB1 = f4sub(wB11, wB01);

        patch_dot(rA0.x, rA0.y, rA1.x, rA1.y, K1, K2h, K3h, K4, P1, dA0, acc);
        patch_dot(rA0.z, rA0.w, rA1.z, rA1.w, K1, K2h, K3h, K4, P1, dA1, acc);
        patch_dot(rB0.x, rB0.y, rB1.x, rB1.y, K1, K2h, K3h, K4, P1, dB0, acc);
        patch_dot(rB0.z, rB0.w, rB1.z, rB1.w, K1, K2h, K3h, K4, P1, dB1, acc);
    }

    // deterministic reduction: warp shuffle -> smem -> short warp-0 stage
#pragma unroll
    for (int off = 16; off > 0; off >>= 1)
        acc += __shfl_down_sync(0xFFFFFFFFu, acc, off);

    __shared__ float warpred[BLK / 32];   // 20 entries
    if ((tid & 31) == 0) warpred[tid >> 5] = acc;
    __syncthreads();

    if (tid < 32) {
        // fold 20 -> 10 with one add, then 4 shuffle levels (8,4,2,1)
        float v = 0.f;
        if (tid < 10) v = warpred[tid] + warpred[tid + 10];
#pragma unroll
        for (int off = 8; off > 0; off >>= 1)
            v += __shfl_down_sync(0xFFFFFFFFu, v, off);
        if (tid == 0) {
            const float d  = v + dbias;                 // l1 - l0
            const float ad = fabsf(d);
            const float t  = __logf(1.f + __expf(-ad)); // log1p(e^-|d|)
            const float lo = -(ad + t);                 // smaller logit
            const float hi = -t;                        // larger logit
            float2 o;
            o.x = (d >= 0.f) ? lo : hi;
            o.y = (d >= 0.f) ? hi : lo;
            *reinterpret_cast<float2*>(out + b * 2) = o;
        }
    }
}

extern "C" void kernel_launch(void* const* d_in, const int* in_sizes, int n_in,
                              void* d_out, int out_size)
{
    (void)in_sizes; (void)n_in; (void)out_size;
    const float* x    = (const float*)d_in[0];  // [64,100,100]
    const float* W    = (const float*)d_in[1];  // [2,10000]
    const float* bias = (const float*)d_in[2];  // [2]
    const float* qp   = (const float*)d_in[3];  // [6]

    fused_kernel<<<64, BLK>>>(x, W, bias, qp, (float*)d_out);
}

// round 13
// speedup vs baseline: 1.0435x; 1.0435x over previous
#include <cuda_runtime.h>
#include <math.h>

// Closed-form collapse of the 4-qubit circuit, product-to-sum trig:
//   a  = t1 + p1,  u = cos(a-t0),  v = cos(a+t0)
//   m0 = cos(p4)cos(p0)cos(t0) + (sin(p4)/2)(v - u)
//   m1 = (cos(p0)/2)(u + v)
//   m2 = cos(t2)
//   m3 = cos(p3)cos(t2)cos(t3)
// t2,t3 are raw pixels in [0,1): cos via even minimax poly on the FMA pipe.
// 2-class log_softmax needs only d = l1 - l0 -> single dot vs dW = W[1]-W[0].
//
// grid=64 (one block per image), 1024 threads (32 warps, HW max).
// Threads 0..1023 handle pair tid; threads 0..225 also handle pair 1024+tid.

#define BLK    1024
#define PAIRS  1250
#define EXTRA  (PAIRS - BLK)   // 226

// cos(t) for t in [0,1]: even minimax poly, |err| ~ 1e-6
__device__ __forceinline__ float cos01(float t) {
    const float s = t * t;
    return fmaf(s, fmaf(s, fmaf(s, -1.3853704e-3f, 4.1663687e-2f),
                        -4.9999905e-1f), 9.9999994e-1f);
}

__device__ __forceinline__ void patch_dot(
    float t0, float t1, float t2, float t3,
    float K1, float K2h, float K3h, float K4, float P1,
    const float4& dw, float& acc)
{
    const float a   = t1 + P1;
    const float c0  = __cosf(t0);
    const float u   = __cosf(a - t0);
    const float v   = __cosf(a + t0);
    const float ct2 = cos01(t2);          // FMA pipe
    const float ct3 = cos01(t3);          // FMA pipe
    const float m0  = fmaf(K1, c0, K2h * (v - u));
    const float m1  = K3h * (u + v);
    const float m3  = K4 * ct2 * ct3;
    acc = fmaf(m0, dw.x, fmaf(m1, dw.y, fmaf(ct2, dw.z, fmaf(m3, dw.w, acc))));
}

__device__ __forceinline__ float4 f4sub(const float4 a, const float4 b) {
    return make_float4(a.x - b.x, a.y - b.y, a.z - b.z, a.w - b.w);
}

// process one patch-pair (pair index q) for image base pointers
__device__ __forceinline__ void do_pair(
    int q, const float* __restrict__ xb, const float* __restrict__ W,
    float K1, float K2h, float K3h, float K4, float P1, float& acc)
{
    const int i  = q / 25;               // patch row 0..49
    const int jp = q - i * 25;           // pair column 0..24
    const int p  = i * 50 + 2 * jp;      // patch index

    const float* xA = xb + 200 * i + 4 * jp;
    const float* wA = W + p * 4;

    const float4 r0  = *reinterpret_cast<const float4*>(xA);
    const float4 r1  = *reinterpret_cast<const float4*>(xA + 100);
    const float4 w00 = *reinterpret_cast<const float4*>(wA);
    const float4 w01 = *reinterpret_cast<const float4*>(wA + 4);
    const float4 w10 = *reinterpret_cast<const float4*>(wA + 10000);
    const float4 w11 = *reinterpret_cast<const float4*>(wA + 10004);

    const float4 d0 = f4sub(w10, w00);
    const float4 d1 = f4sub(w11, w01);

    patch_dot(r0.x, r0.y, r1.x, r1.y, K1, K2h, K3h, K4, P1, d0, acc);
    patch_dot(r0.z, r0.w, r1.z, r1.w, K1, K2h, K3h, K4, P1, d1, acc);
}

__global__ __launch_bounds__(BLK) void fused_kernel(
    const float* __restrict__ x,
    const float* __restrict__ W,
    const float* __restrict__ bias,
    const float* __restrict__ qp,
    float* __restrict__ out)
{
    const int tid = threadIdx.x;
    const int b   = blockIdx.x;

    // Hoisted: bias difference (overlaps main load wave; avoids tail latency)
    const float dbias = bias[1] - bias[0];

    // Circuit constants (broadcast loads; MUFU overlaps x-load latency)
    float sp4, cp4;
    __sincosf(qp[4], &sp4, &cp4);
    const float cp0 = __cosf(qp[0]);
    const float K4  = __cosf(qp[3]);
    const float P1  = qp[1];
    const float K1  = cp4 * cp0;
    const float K2h = 0.5f * sp4;
    const float K3h = 0.5f * cp0;

    const float* xb = x + b * 10000;

    float acc = 0.f;
    do_pair(tid, xb, W, K1, K2h, K3h, K4, P1, acc);
    if (tid < EXTRA)
        do_pair(tid + BLK, xb, W, K1, K2h, K3h, K4, P1, acc);

    // deterministic reduction: warp shuffle -> smem -> warp 0 (exactly 32)
#pragma unroll
    for (int off = 16; off > 0; off >>= 1)
        acc += __shfl_down_sync(0xFFFFFFFFu, acc, off);

    __shared__ float warpred[BLK / 32];   // 32 entries
    if ((tid & 31) == 0) warpred[tid >> 5] = acc;
    __syncthreads();

    if (tid < 32) {
        float v = warpred[tid];
#pragma unroll
        for (int off = 16; off > 0; off >>= 1)
            v += __shfl_down_sync(0xFFFFFFFFu, v, off);
        if (tid == 0) {
            const float d  = v + dbias;                 // l1 - l0
            const float ad = fabsf(d);
            const float t  = __logf(1.f + __expf(-ad)); // log1p(e^-|d|)
            const float lo = -(ad + t);                 // smaller logit
            const float hi = -t;                        // larger logit
            float2 o;
            o.x = (d >= 0.f) ? lo : hi;
            o.y = (d >= 0.f) ? hi : lo;
            *reinterpret_cast<float2*>(out + b * 2) = o;
        }
    }
}

extern "C" void kernel_launch(void* const* d_in, const int* in_sizes, int n_in,
                              void* d_out, int out_size)
{
    (void)in_sizes; (void)n_in; (void)out_size;
    const float* x    = (const float*)d_in[0];  // [64,100,100]
    const float* W    = (const float*)d_in[1];  // [2,10000]
    const float* bias = (const float*)d_in[2];  // [2]
    const float* qp   = (const float*)d_in[3];  // [6]

    fused_kernel<<<64, BLK>>>(x, W, bias, qp, (float*)d_out);
}